// round 10
// baseline (speedup 1.0000x reference)
#include <cuda_runtime.h>
#include <cuda_bf16.h>
#include <cstdint>

// Problem dims
#define BSZ   512
#define HID   512
#define TSEQ  128
#define HOR   24
#define INDIM 2

// Tiling
#define BM    128     // batch rows per CTA
#define BN    64      // gate cols per CTA = 4 quadrants x 16 hidden cols
#define BK    128     // k-chunk per pipeline iter
#define NTHR  256     // 8 warps: 4x2 grid, warp tile 32x32
#define BH (BSZ*HID)
#define SROW  136     // padded smem row: 128 + 8 bf16 = 272B, conflict-free ldmatrix

// 2-stage smem ring
#define STAGES      2
#define A_PLANE     (BM*SROW*2)            // 34816 B
#define B_PLANE     (BN*SROW*2)            // 17408 B
#define SM_AH       0
#define SM_AL       (A_PLANE)
#define SM_BHI      (2*A_PLANE)
#define SM_BLO      (2*A_PLANE + B_PLANE)
#define STAGE_BYTES (2*A_PLANE + 2*B_PLANE)   // 104448
#define SMEM_DYN    (STAGES*STAGE_BYTES)      // 208896
#define SXI_OFF     36864                      // xi scratch (after gm overlay 34816)

// ---------------- device scratch (static) ----------------------------------
__device__ __nv_bfloat16 g_hs1h[TSEQ*BH];
__device__ __nv_bfloat16 g_hs1l[TSEQ*BH];
__device__ __nv_bfloat16 g_h1ah[BH], g_h1al[BH], g_h1bh[BH], g_h1bl[BH];
__device__ __nv_bfloat16 g_h2ah[BH], g_h2al[BH], g_h2bh[BH], g_h2bl[BH];
__device__ __nv_bfloat16 g_zbf[BH];
__device__ float g_c1[BH], g_c2[BH];
__device__ float g_decin[BSZ*INDIM];
// split + tile-reordered weights: row = tile*64 + q*16 + hcd, col = k
// 0=eWhh0 1=eWih1 2=eWhh1 3=dWhh0 4=dWih1 5=dWhh1
__device__ __nv_bfloat16 g_wh[6][4*HID*HID];
__device__ __nv_bfloat16 g_wl[6][4*HID*HID];
// combined biases bih+bhh: 0=enc0 1=enc1 2=dec0 3=dec1
__device__ float g_bsum[4][4*HID];

// ---------------- helpers ---------------------------------------------------
__device__ __forceinline__ float fast_sigmoid(float x) {
    return 1.0f / (1.0f + __expf(-x));
}
__device__ __forceinline__ float fast_tanh(float x) {
    return 1.0f - 2.0f / (__expf(2.0f * x) + 1.0f);
}
__device__ __forceinline__ void mma_bf16(float* c, const unsigned* a, const unsigned* b) {
    asm volatile(
        "mma.sync.aligned.m16n8k16.row.col.f32.bf16.bf16.f32 "
        "{%0,%1,%2,%3}, {%4,%5,%6,%7}, {%8,%9}, {%0,%1,%2,%3};\n"
        : "+f"(c[0]), "+f"(c[1]), "+f"(c[2]), "+f"(c[3])
        : "r"(a[0]), "r"(a[1]), "r"(a[2]), "r"(a[3]), "r"(b[0]), "r"(b[1]));
}
__device__ __forceinline__ void ldsm4(unsigned* r, const void* p) {
    unsigned addr = (unsigned)__cvta_generic_to_shared(p);
    asm volatile("ldmatrix.sync.aligned.m8n8.x4.shared.b16 {%0,%1,%2,%3}, [%4];"
        : "=r"(r[0]), "=r"(r[1]), "=r"(r[2]), "=r"(r[3]) : "r"(addr));
}
__device__ __forceinline__ void cp16(void* smem, const void* gmem) {
    unsigned s = (unsigned)__cvta_generic_to_shared(smem);
    asm volatile("cp.async.cg.shared.global [%0], [%1], 16;\n" :: "r"(s), "l"(gmem));
}
__device__ __forceinline__ void cp_commit() {
    asm volatile("cp.async.commit_group;\n");
}
template<int N> __device__ __forceinline__ void cp_wait() {
    asm volatile("cp.async.wait_group %0;\n" :: "n"(N));
}

// Stage one (A 128xBK, W 64xBK) hi/lo tile set into ring buffer `buf`.
__device__ __forceinline__ void stage_tiles(
    char* smem, int buf,
    const __nv_bfloat16* __restrict__ Ah, const __nv_bfloat16* __restrict__ Al,
    const __nv_bfloat16* __restrict__ Wh, const __nv_bfloat16* __restrict__ Wl,
    int b0, int k0)
{
    char* base = smem + buf * STAGE_BYTES;
    const int tid = threadIdx.x;
    #pragma unroll
    for (int i = 0; i < 8; i++) {
        int idx = tid + i * NTHR;        // 0..2047 = 128 rows x 16 chunks of 16B
        int row = idx >> 4, ch = idx & 15;
        int so = (row * SROW + ch * 8) * 2;
        const int go = (b0 + row) * HID + k0 + ch * 8;
        cp16(base + SM_AH + so, Ah + go);
        cp16(base + SM_AL + so, Al + go);
    }
    #pragma unroll
    for (int i = 0; i < 4; i++) {
        int idx = tid + i * NTHR;        // 0..1023 = 64 rows x 16 chunks
        int row = idx >> 4, ch = idx & 15;
        int so = (row * SROW + ch * 8) * 2;
        const int go = row * HID + k0 + ch * 8;
        cp16(base + SM_BHI + so, Wh + go);
        cp16(base + SM_BLO + so, Wl + go);
    }
    cp_commit();
}

// Load all fragments for one k16 step `kk` into the given buffers.
__device__ __forceinline__ void ld_frags(
    char* base, int kk, int wm, int wn,
    int a_row, int a_col, int b_row, int b_col,
    unsigned ah[2][4], unsigned al[2][4], unsigned bh[2][4], unsigned bl[2][4])
{
    #pragma unroll
    for (int mt = 0; mt < 2; mt++) {
        int off = ((wm * 32 + mt * 16 + a_row) * SROW + kk * 16 + a_col) * 2;
        ldsm4(ah[mt], base + SM_AH + off);
        ldsm4(al[mt], base + SM_AL + off);
    }
    #pragma unroll
    for (int p = 0; p < 2; p++) {
        int off = ((wn * 32 + p * 16 + b_row) * SROW + kk * 16 + b_col) * 2;
        ldsm4(bh[p], base + SM_BHI + off);
        ldsm4(bl[p], base + SM_BLO + off);
    }
}

__device__ __forceinline__ void mma_all(
    float acc[2][4][4],
    unsigned ah[2][4], unsigned al[2][4], unsigned bh[2][4], unsigned bl[2][4])
{
    // pass-major: same-accumulator HMMAs spaced by 8 issues
    #pragma unroll
    for (int mt = 0; mt < 2; mt++)
        #pragma unroll
        for (int nb = 0; nb < 4; nb++)
            mma_bf16(acc[mt][nb], ah[mt], &bh[nb >> 1][(nb & 1) * 2]);
    #pragma unroll
    for (int mt = 0; mt < 2; mt++)
        #pragma unroll
        for (int nb = 0; nb < 4; nb++)
            mma_bf16(acc[mt][nb], ah[mt], &bl[nb >> 1][(nb & 1) * 2]);
    #pragma unroll
    for (int mt = 0; mt < 2; mt++)
        #pragma unroll
        for (int nb = 0; nb < 4; nb++)
            mma_bf16(acc[mt][nb], al[mt], &bh[nb >> 1][(nb & 1) * 2]);
}

// ---------------- fused LSTM step (mma.sync, 3-pass bf16 split) -------------
// mode 0: xi from x1 buffer (fp32, stride lda1), weights Wx [2048,2]; NI=4
// mode 1: input proj via full K=512 GEMM on (A1h/A1l, W1h/W1l); NI=8
// mode 2: xi = pred(h2prev) computed in-kernel; A1h/A1l = h2prev planes,
//         x1 = fcW (fp32 [2,512]), W1h = (bf16*)fcb; writes outp[.,step]; NI=4
// mode 3: no input term (decoder s=0, dec_in0 = 0); NI=4
__global__ void __launch_bounds__(NTHR)
lstm_step(const __nv_bfloat16* __restrict__ A1h, const __nv_bfloat16* __restrict__ A1l,
          const __nv_bfloat16* __restrict__ W1h, const __nv_bfloat16* __restrict__ W1l,
          const float* __restrict__ x1, int lda1, const float* __restrict__ Wx,
          const __nv_bfloat16* __restrict__ Hinh, const __nv_bfloat16* __restrict__ Hinl,
          const __nv_bfloat16* __restrict__ Whh_h, const __nv_bfloat16* __restrict__ Whh_l,
          const float* __restrict__ bsum,
          __nv_bfloat16* __restrict__ Houth, __nv_bfloat16* __restrict__ Houtl,
          float* __restrict__ C, int mode, float* __restrict__ outp, int step)
{
    extern __shared__ char smem[];
    const int tid = threadIdx.x;
    const int wid = tid >> 5, lane = tid & 31;
    const int wm = wid >> 1, wn = wid & 1;   // 4x2 warps: 32 rows x 32 cols each
    const int hc0 = blockIdx.x * 16;
    const int b0  = blockIdx.y * BM;
    const int wt  = blockIdx.x * BN * HID;   // weight tile offset
    const int NI  = (mode == 1) ? 8 : 4;

    // ldmatrix lane addressing
    const int a_row = (lane & 7) + ((lane >> 3) & 1) * 8;
    const int a_col = (lane >> 4) * 8;
    const int b_row = (lane >> 4) * 8 + (lane & 7);
    const int b_col = ((lane >> 3) & 1) * 8;

    auto srcs = [&](int j, const __nv_bfloat16*& sAh, const __nv_bfloat16*& sAl,
                    const __nv_bfloat16*& sWh, const __nv_bfloat16*& sWl, int& k0) {
        if (mode == 1 && j < 4) {
            sAh = A1h; sAl = A1l; sWh = W1h + wt; sWl = W1l + wt; k0 = j * BK;
        } else {
            int jj = (mode == 1) ? j - 4 : j;
            sAh = Hinh; sAl = Hinl; sWh = Whh_h + wt; sWl = Whh_l + wt; k0 = jj * BK;
        }
    };

    float acc[2][4][4];
    #pragma unroll
    for (int mt = 0; mt < 2; mt++)
        #pragma unroll
        for (int nb = 0; nb < 4; nb++)
            #pragma unroll
            for (int r = 0; r < 4; r++) acc[mt][nb][r] = 0.0f;

    // prologue: stage(0)
    {
        const __nv_bfloat16 *a, *al, *w, *wl; int k0;
        srcs(0, a, al, w, wl, k0);
        stage_tiles(smem, 0, a, al, w, wl, b0, k0);
    }

    #pragma unroll 1
    for (int it = 0; it < NI; it++) {
        cp_wait<0>();        // stage(it) complete (only outstanding group)
        __syncthreads();     // all warps done reading stage it-1's buffer
        if (it + 1 < NI) {
            const __nv_bfloat16 *a, *al, *w, *wl; int k0;
            srcs(it + 1, a, al, w, wl, k0);
            stage_tiles(smem, (it + 1) & 1, a, al, w, wl, b0, k0);
        }
        char* base = smem + (it & 1) * STAGE_BYTES;
        // kk-pipelined consume: preload kk+1 fragments while issuing kk's MMAs
        unsigned ah[2][2][4], al2[2][2][4], bh[2][2][4], bl[2][2][4];
        ld_frags(base, 0, wm, wn, a_row, a_col, b_row, b_col,
                 ah[0], al2[0], bh[0], bl[0]);
        #pragma unroll
        for (int kk = 0; kk < 8; kk++) {
            if (kk < 7)
                ld_frags(base, kk + 1, wm, wn, a_row, a_col, b_row, b_col,
                         ah[(kk + 1) & 1], al2[(kk + 1) & 1],
                         bh[(kk + 1) & 1], bl[(kk + 1) & 1]);
            mma_all(acc, ah[kk & 1], al2[kk & 1], bh[kk & 1], bl[kk & 1]);
        }
    }

    // ---- epilogue ----
    float (*gm)[BN + 4] = reinterpret_cast<float (*)[BN + 4]>(smem);
    float* sxi = reinterpret_cast<float*>(smem + SXI_OFF);
    // gm + sxi live in buffer 0's region; last consumed buffer is 1 (NI even),
    // so no collision with warps still reading their final stage.
    {
        int g = lane >> 2, t = lane & 3;
        #pragma unroll
        for (int mt = 0; mt < 2; mt++)
            #pragma unroll
            for (int nb = 0; nb < 4; nb++) {
                int row = wm * 32 + mt * 16 + g;
                int col = wn * 32 + nb * 8 + t * 2;
                gm[row][col]         = acc[mt][nb][0];
                gm[row][col + 1]     = acc[mt][nb][1];
                gm[row + 8][col]     = acc[mt][nb][2];
                gm[row + 8][col + 1] = acc[mt][nb][3];
            }
    }
    if (mode == 2) {
        // xi = pred from h2prev: 2 threads per batch row, k-split 256+256
        int row = tid >> 1, half = tid & 1;
        int b = b0 + row;
        const __nv_bfloat16* ph = A1h + b * HID + half * 256;
        const __nv_bfloat16* pl = A1l + b * HID + half * 256;
        const float* fw = x1 + half * 256;
        float s0 = 0.0f, s1 = 0.0f;
        #pragma unroll 4
        for (int k8 = 0; k8 < 32; k8++) {
            uint4 vh = *reinterpret_cast<const uint4*>(ph + k8 * 8);
            uint4 vl = *reinterpret_cast<const uint4*>(pl + k8 * 8);
            const unsigned* uh = reinterpret_cast<const unsigned*>(&vh);
            const unsigned* ul = reinterpret_cast<const unsigned*>(&vl);
            #pragma unroll
            for (int e = 0; e < 4; e++) {
                float h0 = __bfloat162float(__ushort_as_bfloat16((unsigned short)(uh[e] & 0xffffu)))
                         + __bfloat162float(__ushort_as_bfloat16((unsigned short)(ul[e] & 0xffffu)));
                float h1 = __bfloat162float(__ushort_as_bfloat16((unsigned short)(uh[e] >> 16)))
                         + __bfloat162float(__ushort_as_bfloat16((unsigned short)(ul[e] >> 16)));
                int k = k8 * 8 + e * 2;
                s0 += h0 * fw[k]     + h1 * fw[k + 1];
                s1 += h0 * fw[512 + k] + h1 * fw[512 + k + 1];
            }
        }
        s0 += __shfl_xor_sync(0xffffffffu, s0, 1);
        s1 += __shfl_xor_sync(0xffffffffu, s1, 1);
        if (half == 0) {
            const float* fcb = reinterpret_cast<const float*>(W1h);
            float p0 = s0 + fcb[0], p1 = s1 + fcb[1];
            sxi[row * 2 + 0] = p0;
            sxi[row * 2 + 1] = p1;
            if (blockIdx.x == 0) {
                outp[b * HOR * 2 + step * 2 + 0] = p0;
                outp[b * HOR * 2 + step * 2 + 1] = p1;
            }
        }
    }
    __syncthreads();
    #pragma unroll
    for (int i = 0; i < 8; i++) {
        int idx = tid + i * NTHR;      // 0..2047 over 128 batch x 16 hc
        int hcd = idx & 15, br = idx >> 4;
        int b = b0 + br, hc = hc0 + hcd;
        float gv[4];
        #pragma unroll
        for (int q = 0; q < 4; q++)
            gv[q] = gm[br][q * 16 + hcd] + bsum[q * HID + hc];
        if (mode == 0 || mode == 2) {
            float xi0, xi1;
            if (mode == 0) { xi0 = x1[b * lda1 + 0]; xi1 = x1[b * lda1 + 1]; }
            else           { xi0 = sxi[br * 2 + 0];  xi1 = sxi[br * 2 + 1]; }
            #pragma unroll
            for (int q = 0; q < 4; q++) {
                int gg = q * HID + hc;
                gv[q] += xi0 * Wx[gg * INDIM + 0] + xi1 * Wx[gg * INDIM + 1];
            }
        }
        float ig = fast_sigmoid(gv[0]);
        float fg = fast_sigmoid(gv[1]);
        float gg = fast_tanh(gv[2]);
        float og = fast_sigmoid(gv[3]);
        int ci = b * HID + hc;
        float c = C[ci];
        c = fg * c + ig * gg;
        C[ci] = c;
        float h = og * fast_tanh(c);
        __nv_bfloat16 hh = __float2bfloat16(h);
        Houth[ci] = hh;
        Houtl[ci] = __float2bfloat16(h - __bfloat162float(hh));
    }
}

// One fused conversion kernel: 6 weight matrices -> split/tile-reordered planes.
__global__ void convert_all(const float* __restrict__ s0, const float* __restrict__ s1,
                            const float* __restrict__ s2, const float* __restrict__ s3,
                            const float* __restrict__ s4, const float* __restrict__ s5,
                            __nv_bfloat16* __restrict__ dhb,
                            __nv_bfloat16* __restrict__ dlb)
{
    const int WSZ = 4 * HID * HID;
    int m = blockIdx.x >> 12;                    // matrix index 0..5
    int j = ((blockIdx.x & 4095) << 8) + threadIdx.x;   // 0..WSZ-1
    const float* src;
    switch (m) {
        case 0: src = s0; break;
        case 1: src = s1; break;
        case 2: src = s2; break;
        case 3: src = s3; break;
        case 4: src = s4; break;
        default: src = s5; break;
    }
    int g = j >> 9, k = j & 511;
    int q = g >> 9, hc = g & 511;
    int tile = hc >> 4, hcd = hc & 15;
    int dr = m * WSZ + ((tile * 4 + q) * 16 + hcd) * HID + k;
    float w = src[j];
    __nv_bfloat16 h = __float2bfloat16(w);
    dhb[dr] = h;
    dlb[dr] = __float2bfloat16(w - __bfloat162float(h));
}

// Fused init: zero states + combined biases.
__global__ void setup_init(const float* __restrict__ eb0a, const float* __restrict__ eb0b,
                           const float* __restrict__ eb1a, const float* __restrict__ eb1b,
                           const float* __restrict__ db0a, const float* __restrict__ db0b,
                           const float* __restrict__ db1a, const float* __restrict__ db1b)
{
    int i = blockIdx.x * blockDim.x + threadIdx.x;
    if (i < BH) {
        g_zbf[i] = __ushort_as_bfloat16((unsigned short)0);
        g_c1[i] = 0.0f;
        g_c2[i] = 0.0f;
    }
    if (i < BSZ * INDIM) g_decin[i] = 0.0f;
    if (i < 4 * HID) {
        g_bsum[0][i] = eb0a[i] + eb0b[i];
        g_bsum[1][i] = eb1a[i] + eb1b[i];
        g_bsum[2][i] = db0a[i] + db0b[i];
        g_bsum[3][i] = db1a[i] + db1b[i];
    }
}

// pred[b,k] = (hi+lo)(h2[b,:]) . fcW[k,:] + fcb[k]  (final decoder step only)
__global__ void pred_kernel(const __nv_bfloat16* __restrict__ h2h,
                            const __nv_bfloat16* __restrict__ h2l,
                            const float* __restrict__ fcW,
                            const float* __restrict__ fcb,
                            float* __restrict__ out, int s)
{
    int warp = threadIdx.x >> 5;
    int lane = threadIdx.x & 31;
    int b = blockIdx.x * 4 + warp;
    float a0 = 0.0f, a1 = 0.0f;
    #pragma unroll
    for (int j = lane; j < HID; j += 32) {
        float h = __bfloat162float(h2h[b * HID + j]) + __bfloat162float(h2l[b * HID + j]);
        a0 += h * fcW[j];
        a1 += h * fcW[HID + j];
    }
    #pragma unroll
    for (int o = 16; o; o >>= 1) {
        a0 += __shfl_xor_sync(0xffffffffu, a0, o);
        a1 += __shfl_xor_sync(0xffffffffu, a1, o);
    }
    if (lane == 0) {
        out[b * HOR * 2 + s * 2 + 0] = a0 + fcb[0];
        out[b * HOR * 2 + s * 2 + 1] = a1 + fcb[1];
    }
}

extern "C" void kernel_launch(void* const* d_in, const int* in_sizes, int n_in,
                              void* d_out, int out_size)
{
    const float* x      = (const float*)d_in[0];
    const float* eWih0  = (const float*)d_in[1];
    const float* eWhh0  = (const float*)d_in[2];
    const float* ebih0  = (const float*)d_in[3];
    const float* ebhh0  = (const float*)d_in[4];
    const float* eWih1  = (const float*)d_in[5];
    const float* eWhh1  = (const float*)d_in[6];
    const float* ebih1  = (const float*)d_in[7];
    const float* ebhh1  = (const float*)d_in[8];
    const float* dWih0  = (const float*)d_in[9];
    const float* dWhh0  = (const float*)d_in[10];
    const float* dbih0  = (const float*)d_in[11];
    const float* dbhh0  = (const float*)d_in[12];
    const float* dWih1  = (const float*)d_in[13];
    const float* dWhh1  = (const float*)d_in[14];
    const float* dbih1  = (const float*)d_in[15];
    const float* dbhh1  = (const float*)d_in[16];
    const float* fcW    = (const float*)d_in[17];
    const float* fcb    = (const float*)d_in[18];
    float* out = (float*)d_out;

    __nv_bfloat16 *hs1h, *hs1l, *h1ah, *h1al, *h1bh, *h1bl;
    __nv_bfloat16 *h2ah, *h2al, *h2bh, *h2bl, *zb, *whb, *wlb;
    float *c1, *c2, *bsb;
    cudaGetSymbolAddress((void**)&hs1h, g_hs1h);
    cudaGetSymbolAddress((void**)&hs1l, g_hs1l);
    cudaGetSymbolAddress((void**)&h1ah, g_h1ah);
    cudaGetSymbolAddress((void**)&h1al, g_h1al);
    cudaGetSymbolAddress((void**)&h1bh, g_h1bh);
    cudaGetSymbolAddress((void**)&h1bl, g_h1bl);
    cudaGetSymbolAddress((void**)&h2ah, g_h2ah);
    cudaGetSymbolAddress((void**)&h2al, g_h2al);
    cudaGetSymbolAddress((void**)&h2bh, g_h2bh);
    cudaGetSymbolAddress((void**)&h2bl, g_h2bl);
    cudaGetSymbolAddress((void**)&zb,   g_zbf);
    cudaGetSymbolAddress((void**)&whb,  g_wh);
    cudaGetSymbolAddress((void**)&wlb,  g_wl);
    cudaGetSymbolAddress((void**)&c1,   g_c1);
    cudaGetSymbolAddress((void**)&c2,   g_c2);
    cudaGetSymbolAddress((void**)&bsb,  g_bsum);

    const int WSZ = 4 * HID * HID;
    __nv_bfloat16 *wh_eWhh0 = whb + 0 * WSZ, *wl_eWhh0 = wlb + 0 * WSZ;
    __nv_bfloat16 *wh_eWih1 = whb + 1 * WSZ, *wl_eWih1 = wlb + 1 * WSZ;
    __nv_bfloat16 *wh_eWhh1 = whb + 2 * WSZ, *wl_eWhh1 = wlb + 2 * WSZ;
    __nv_bfloat16 *wh_dWhh0 = whb + 3 * WSZ, *wl_dWhh0 = wlb + 3 * WSZ;
    __nv_bfloat16 *wh_dWih1 = whb + 4 * WSZ, *wl_dWih1 = wlb + 4 * WSZ;
    __nv_bfloat16 *wh_dWhh1 = whb + 5 * WSZ, *wl_dWhh1 = wlb + 5 * WSZ;
    float *bs_e0 = bsb + 0 * 4 * HID, *bs_e1 = bsb + 1 * 4 * HID;
    float *bs_d0 = bsb + 2 * 4 * HID, *bs_d1 = bsb + 3 * 4 * HID;

    cudaFuncSetAttribute(lstm_step, cudaFuncAttributeMaxDynamicSharedMemorySize,
                         SMEM_DYN);

    setup_init<<<(BH + 255) / 256, 256>>>(ebih0, ebhh0, ebih1, ebhh1,
                                          dbih0, dbhh0, dbih1, dbhh1);
    convert_all<<<6 * 4096, 256>>>(eWhh0, eWih1, eWhh1, dWhh0, dWih1, dWhh1,
                                   whb, wlb);

    dim3 grid(HID / 16, BSZ / BM);   // (32, 4) = 128 CTAs

    // Encoder layer 1 (mode 0). h chain lives in hs1 planes.
    for (int t = 0; t < TSEQ; t++) {
        const __nv_bfloat16* hinh = t ? (hs1h + (size_t)(t - 1) * BH) : zb;
        const __nv_bfloat16* hinl = t ? (hs1l + (size_t)(t - 1) * BH) : zb;
        lstm_step<<<grid, NTHR, SMEM_DYN>>>(
            nullptr, nullptr, nullptr, nullptr,
            x + t * INDIM, TSEQ * INDIM, eWih0,
            hinh, hinl, wh_eWhh0, wl_eWhh0, bs_e0,
            hs1h + (size_t)t * BH, hs1l + (size_t)t * BH, c1, 0, nullptr, 0);
    }
    // Encoder layer 2 (mode 1): final state ends in h2b (T even)
    for (int t = 0; t < TSEQ; t++) {
        const __nv_bfloat16* hinh = (t == 0) ? zb : ((t & 1) ? h2ah : h2bh);
        const __nv_bfloat16* hinl = (t == 0) ? zb : ((t & 1) ? h2al : h2bl);
        __nv_bfloat16* houth = (t & 1) ? h2bh : h2ah;
        __nv_bfloat16* houtl = (t & 1) ? h2bl : h2al;
        lstm_step<<<grid, NTHR, SMEM_DYN>>>(
            hs1h + (size_t)t * BH, hs1l + (size_t)t * BH, wh_eWih1, wl_eWih1,
            nullptr, 0, nullptr,
            hinh, hinl, wh_eWhh1, wl_eWhh1, bs_e1, houth, houtl, c2, 1, nullptr, 0);
    }
    // Decoder
    for (int s = 0; s < HOR; s++) {
        const __nv_bfloat16* h1inh = (s == 0) ? (hs1h + (size_t)(TSEQ - 1) * BH)
                                              : ((s & 1) ? h1ah : h1bh);
        const __nv_bfloat16* h1inl = (s == 0) ? (hs1l + (size_t)(TSEQ - 1) * BH)
                                              : ((s & 1) ? h1al : h1bl);
        __nv_bfloat16* h1outh = (s & 1) ? h1bh : h1ah;
        __nv_bfloat16* h1outl = (s & 1) ? h1bl : h1al;
        if (s == 0) {
            // dec_in0 = 0: mode 3 (no input term)
            lstm_step<<<grid, NTHR, SMEM_DYN>>>(
                nullptr, nullptr, nullptr, nullptr,
                nullptr, 0, nullptr,
                h1inh, h1inl, wh_dWhh0, wl_dWhh0, bs_d0, h1outh, h1outl,
                c1, 3, nullptr, 0);
        } else {
            // mode 2: xi = pred(h2 of step s-1), also writes out[., s-1]
            const __nv_bfloat16* h2ph = ((s - 1) & 1) ? h2bh : h2ah;
            const __nv_bfloat16* h2pl = ((s - 1) & 1) ? h2bl : h2al;
            lstm_step<<<grid, NTHR, SMEM_DYN>>>(
                h2ph, h2pl, (const __nv_bfloat16*)fcb, nullptr,
                fcW, 0, dWih0,
                h1inh, h1inl, wh_dWhh0, wl_dWhh0, bs_d0, h1outh, h1outl,
                c1, 2, out, s - 1);
        }

        const __nv_bfloat16* h2inh = (s == 0) ? h2bh : ((s & 1) ? h2ah : h2bh);
        const __nv_bfloat16* h2inl = (s == 0) ? h2bl : ((s & 1) ? h2al : h2bl);
        __nv_bfloat16* h2outh = (s & 1) ? h2bh : h2ah;
        __nv_bfloat16* h2outl = (s & 1) ? h2bl : h2al;
        lstm_step<<<grid, NTHR, SMEM_DYN>>>(
            h1outh, h1outl, wh_dWih1, wl_dWih1,
            nullptr, 0, nullptr,
            h2inh, h2inl, wh_dWhh1, wl_dWhh1, bs_d1, h2outh, h2outl, c2, 1,
            nullptr, 0);
    }
    // Final prediction (step 23) from h2 of s=23 (odd -> h2b)
    pred_kernel<<<BSZ / 4, 128>>>(h2bh, h2bl, fcW, fcb, out, HOR - 1);
}

// round 15
// speedup vs baseline: 1.6149x; 1.6149x over previous
#include <cuda_runtime.h>
#include <cuda_bf16.h>
#include <cstdint>

// Problem dims
#define BSZ   512
#define HID   512
#define TSEQ  128
#define HOR   24
#define INDIM 2

// Tiling
#define BM    128     // batch rows per CTA
#define BN    64      // gate cols per CTA = 4 quadrants x 16 hidden cols
#define BK    64      // k-chunk per pipeline iter
#define NTHR  512     // 16 warps: 4x4 grid, warp tile 32x16
#define BH (BSZ*HID)
#define SROW  72      // padded smem row: 64 + 8 bf16 = 144B, conflict-free ldmatrix

// 4-stage smem ring
#define STAGES      4
#define A_PLANE     (BM*SROW*2)            // 18432 B
#define B_PLANE     (BN*SROW*2)            // 9216 B
#define SM_AH       0
#define SM_AL       (A_PLANE)
#define SM_BHI      (2*A_PLANE)
#define SM_BLO      (2*A_PLANE + B_PLANE)
#define STAGE_BYTES (2*A_PLANE + 2*B_PLANE)   // 55296
#define SMEM_DYN    (STAGES*STAGE_BYTES)      // 221184
#define SXI_OFF     34816                      // xi scratch, after gm overlay

// ---------------- device scratch (static) ----------------------------------
__device__ __nv_bfloat16 g_hs1h[TSEQ*BH];
__device__ __nv_bfloat16 g_hs1l[TSEQ*BH];
__device__ __nv_bfloat16 g_h1ah[BH], g_h1al[BH], g_h1bh[BH], g_h1bl[BH];
__device__ __nv_bfloat16 g_h2ah[BH], g_h2al[BH], g_h2bh[BH], g_h2bl[BH];
__device__ __nv_bfloat16 g_zbf[BH];
__device__ float g_c1[BH], g_c2[BH];
// split + tile-reordered weights: row = tile*64 + q*16 + hcd, col = k
// 0=eWhh0 1=eWih1 2=eWhh1 3=dWhh0 4=dWih1 5=dWhh1
__device__ __nv_bfloat16 g_wh[6][4*HID*HID];
__device__ __nv_bfloat16 g_wl[6][4*HID*HID];
// combined biases bih+bhh: 0=enc0 1=enc1 2=dec0 3=dec1
__device__ float g_bsum[4][4*HID];

// ---------------- helpers ---------------------------------------------------
__device__ __forceinline__ float fast_sigmoid(float x) {
    return 1.0f / (1.0f + __expf(-x));
}
__device__ __forceinline__ float fast_tanh(float x) {
    return 1.0f - 2.0f / (__expf(2.0f * x) + 1.0f);
}
__device__ __forceinline__ void mma_bf16(float* c, const unsigned* a, const unsigned* b) {
    asm volatile(
        "mma.sync.aligned.m16n8k16.row.col.f32.bf16.bf16.f32 "
        "{%0,%1,%2,%3}, {%4,%5,%6,%7}, {%8,%9}, {%0,%1,%2,%3};\n"
        : "+f"(c[0]), "+f"(c[1]), "+f"(c[2]), "+f"(c[3])
        : "r"(a[0]), "r"(a[1]), "r"(a[2]), "r"(a[3]), "r"(b[0]), "r"(b[1]));
}
__device__ __forceinline__ void ldsm4(unsigned* r, const void* p) {
    unsigned addr = (unsigned)__cvta_generic_to_shared(p);
    asm volatile("ldmatrix.sync.aligned.m8n8.x4.shared.b16 {%0,%1,%2,%3}, [%4];"
        : "=r"(r[0]), "=r"(r[1]), "=r"(r[2]), "=r"(r[3]) : "r"(addr));
}
__device__ __forceinline__ void cp16(void* smem, const void* gmem) {
    unsigned s = (unsigned)__cvta_generic_to_shared(smem);
    asm volatile("cp.async.cg.shared.global [%0], [%1], 16;\n" :: "r"(s), "l"(gmem));
}
__device__ __forceinline__ void cp_commit() {
    asm volatile("cp.async.commit_group;\n");
}
template<int N> __device__ __forceinline__ void cp_wait() {
    asm volatile("cp.async.wait_group %0;\n" :: "n"(N));
}

// Stage one (A 128xBK, W 64xBK) hi/lo tile set into ring buffer `buf`.
__device__ __forceinline__ void stage_tiles(
    char* smem, int buf,
    const __nv_bfloat16* __restrict__ Ah, const __nv_bfloat16* __restrict__ Al,
    const __nv_bfloat16* __restrict__ Wh, const __nv_bfloat16* __restrict__ Wl,
    int b0, int k0)
{
    char* base = smem + buf * STAGE_BYTES;
    const int tid = threadIdx.x;
    #pragma unroll
    for (int i = 0; i < 2; i++) {
        int idx = tid + i * NTHR;        // 0..1023 = 128 rows x 8 chunks of 16B
        int row = idx >> 3, ch = idx & 7;
        int so = (row * SROW + ch * 8) * 2;
        const int go = (b0 + row) * HID + k0 + ch * 8;
        cp16(base + SM_AH + so, Ah + go);
        cp16(base + SM_AL + so, Al + go);
    }
    {
        int idx = tid;                   // 0..511 = 64 rows x 8 chunks
        int row = idx >> 3, ch = idx & 7;
        int so = (row * SROW + ch * 8) * 2;
        const int go = row * HID + k0 + ch * 8;
        cp16(base + SM_BHI + so, Wh + go);
        cp16(base + SM_BLO + so, Wl + go);
    }
    cp_commit();
}

// ---------------- fused LSTM step (mma.sync, 3-pass bf16 split) -------------
// mode 0: xi from x1 buffer (fp32, stride lda1), weights Wx [2048,2]; NI=8
// mode 1: input proj via full K=512 GEMM on (A1h/A1l, W1h/W1l); NI=16
// mode 2: xi = pred(h2prev) in-kernel; A1h/A1l = h2prev planes,
//         x1 = fcW (fp32 [2,512]), W1h = (bf16*)fcb; writes outp[.,step]; NI=8
// mode 3: no input term (decoder s=0, dec_in0 = 0); NI=8
__global__ void __launch_bounds__(NTHR)
lstm_step(const __nv_bfloat16* __restrict__ A1h, const __nv_bfloat16* __restrict__ A1l,
          const __nv_bfloat16* __restrict__ W1h, const __nv_bfloat16* __restrict__ W1l,
          const float* __restrict__ x1, int lda1, const float* __restrict__ Wx,
          const __nv_bfloat16* __restrict__ Hinh, const __nv_bfloat16* __restrict__ Hinl,
          const __nv_bfloat16* __restrict__ Whh_h, const __nv_bfloat16* __restrict__ Whh_l,
          const float* __restrict__ bsum,
          __nv_bfloat16* __restrict__ Houth, __nv_bfloat16* __restrict__ Houtl,
          float* __restrict__ C, int mode, float* __restrict__ outp, int step)
{
    extern __shared__ char smem[];
    const int tid = threadIdx.x;
    const int wid = tid >> 5, lane = tid & 31;
    const int wm = wid >> 2, wn = wid & 3;   // 4x4 warps: 32 rows x 16 cols each
    const int hc0 = blockIdx.x * 16;
    const int b0  = blockIdx.y * BM;
    const int wt  = blockIdx.x * BN * HID;   // weight tile offset
    const int NI  = (mode == 1) ? 16 : 8;

    // ldmatrix lane addressing
    const int a_row = (lane & 7) + ((lane >> 3) & 1) * 8;
    const int a_col = (lane >> 4) * 8;
    const int b_row = (lane >> 4) * 8 + (lane & 7);
    const int b_col = ((lane >> 3) & 1) * 8;

    auto srcs = [&](int j, const __nv_bfloat16*& sAh, const __nv_bfloat16*& sAl,
                    const __nv_bfloat16*& sWh, const __nv_bfloat16*& sWl, int& k0) {
        if (mode == 1 && j < 8) {
            sAh = A1h; sAl = A1l; sWh = W1h + wt; sWl = W1l + wt; k0 = j * BK;
        } else {
            int jj = (mode == 1) ? j - 8 : j;
            sAh = Hinh; sAl = Hinl; sWh = Whh_h + wt; sWl = Whh_l + wt; k0 = jj * BK;
        }
    };

    float acc[2][2][4];
    #pragma unroll
    for (int mt = 0; mt < 2; mt++)
        #pragma unroll
        for (int nb = 0; nb < 2; nb++)
            #pragma unroll
            for (int r = 0; r < 4; r++) acc[mt][nb][r] = 0.0f;

    // prologue: fill 3 of the 4 ring slots
    #pragma unroll
    for (int p = 0; p < 3; p++) {
        const __nv_bfloat16 *a, *al, *w, *wl; int k0;
        srcs(p, a, al, w, wl, k0);
        stage_tiles(smem, p, a, al, w, wl, b0, k0);
    }

    #pragma unroll 1
    for (int it = 0; it < NI; it++) {
        // complete cp.async group `it`
        if (NI - it >= 3)       cp_wait<2>();
        else if (NI - it == 2)  cp_wait<1>();
        else                    cp_wait<0>();
        __syncthreads();   // all warps see stage it; all done reading stage it-1
        if (it + 3 < NI) {
            const __nv_bfloat16 *a, *al, *w, *wl; int k0;
            srcs(it + 3, a, al, w, wl, k0);
            stage_tiles(smem, (it + 3) & 3, a, al, w, wl, b0, k0);
        }
        char* base = smem + (it & 3) * STAGE_BYTES;
        #pragma unroll
        for (int kk = 0; kk < 4; kk++) {
            unsigned ah[2][4], al[2][4], bh[4], bl[4];
            #pragma unroll
            for (int mt = 0; mt < 2; mt++) {
                int off = ((wm * 32 + mt * 16 + a_row) * SROW + kk * 16 + a_col) * 2;
                ldsm4(ah[mt], base + SM_AH + off);
                ldsm4(al[mt], base + SM_AL + off);
            }
            {
                int off = ((wn * 16 + b_row) * SROW + kk * 16 + b_col) * 2;
                ldsm4(bh, base + SM_BHI + off);
                ldsm4(bl, base + SM_BLO + off);
            }
            // pass-major: same-accumulator HMMAs spaced by 4 issues
            #pragma unroll
            for (int mt = 0; mt < 2; mt++)
                #pragma unroll
                for (int nb = 0; nb < 2; nb++)
                    mma_bf16(acc[mt][nb], ah[mt], &bh[nb * 2]);
            #pragma unroll
            for (int mt = 0; mt < 2; mt++)
                #pragma unroll
                for (int nb = 0; nb < 2; nb++)
                    mma_bf16(acc[mt][nb], ah[mt], &bl[nb * 2]);
            #pragma unroll
            for (int mt = 0; mt < 2; mt++)
                #pragma unroll
                for (int nb = 0; nb < 2; nb++)
                    mma_bf16(acc[mt][nb], al[mt], &bh[nb * 2]);
        }
    }

    // ---- epilogue: gate transpose through smem, then fused cell update ----
    // gm [0,34816) + sxi [34816,35840) live in ring buffer 0, whose last
    // mainloop read was >=3 barriers ago for NI in {8,16}.
    float (*gm)[BN + 4] = reinterpret_cast<float (*)[BN + 4]>(smem);
    float* sxi = reinterpret_cast<float*>(smem + SXI_OFF);
    __syncthreads();
    {
        int g = lane >> 2, t = lane & 3;
        #pragma unroll
        for (int mt = 0; mt < 2; mt++)
            #pragma unroll
            for (int nb = 0; nb < 2; nb++) {
                int row = wm * 32 + mt * 16 + g;
                int col = wn * 16 + nb * 8 + t * 2;
                gm[row][col]         = acc[mt][nb][0];
                gm[row][col + 1]     = acc[mt][nb][1];
                gm[row + 8][col]     = acc[mt][nb][2];
                gm[row + 8][col + 1] = acc[mt][nb][3];
            }
    }
    if (mode == 2) {
        // xi = pred from h2prev: 4 threads per batch row, k-split 4x128
        int row = tid >> 2, quarter = tid & 3;
        int b = b0 + row;
        const __nv_bfloat16* ph = A1h + b * HID + quarter * 128;
        const __nv_bfloat16* pl = A1l + b * HID + quarter * 128;
        const float* fw = x1 + quarter * 128;
        float s0 = 0.0f, s1 = 0.0f;
        #pragma unroll 4
        for (int k8 = 0; k8 < 16; k8++) {
            uint4 vh = *reinterpret_cast<const uint4*>(ph + k8 * 8);
            uint4 vl = *reinterpret_cast<const uint4*>(pl + k8 * 8);
            const unsigned* uh = reinterpret_cast<const unsigned*>(&vh);
            const unsigned* ul = reinterpret_cast<const unsigned*>(&vl);
            #pragma unroll
            for (int e = 0; e < 4; e++) {
                float h0 = __bfloat162float(__ushort_as_bfloat16((unsigned short)(uh[e] & 0xffffu)))
                         + __bfloat162float(__ushort_as_bfloat16((unsigned short)(ul[e] & 0xffffu)));
                float h1 = __bfloat162float(__ushort_as_bfloat16((unsigned short)(uh[e] >> 16)))
                         + __bfloat162float(__ushort_as_bfloat16((unsigned short)(ul[e] >> 16)));
                int k = k8 * 8 + e * 2;
                s0 += h0 * fw[k]       + h1 * fw[k + 1];
                s1 += h0 * fw[512 + k] + h1 * fw[512 + k + 1];
            }
        }
        s0 += __shfl_xor_sync(0xffffffffu, s0, 1);
        s1 += __shfl_xor_sync(0xffffffffu, s1, 1);
        s0 += __shfl_xor_sync(0xffffffffu, s0, 2);
        s1 += __shfl_xor_sync(0xffffffffu, s1, 2);
        if (quarter == 0) {
            const float* fcb = reinterpret_cast<const float*>(W1h);
            float p0 = s0 + fcb[0], p1 = s1 + fcb[1];
            sxi[row * 2 + 0] = p0;
            sxi[row * 2 + 1] = p1;
            if (blockIdx.x == 0) {
                outp[b * HOR * 2 + step * 2 + 0] = p0;
                outp[b * HOR * 2 + step * 2 + 1] = p1;
            }
        }
    }
    __syncthreads();
    #pragma unroll
    for (int i = 0; i < 4; i++) {
        int idx = tid + i * NTHR;      // 0..2047 over 128 batch x 16 hc
        int hcd = idx & 15, br = idx >> 4;
        int b = b0 + br, hc = hc0 + hcd;
        float gv[4];
        #pragma unroll
        for (int q = 0; q < 4; q++)
            gv[q] = gm[br][q * 16 + hcd] + bsum[q * HID + hc];
        if (mode == 0 || mode == 2) {
            float xi0, xi1;
            if (mode == 0) { xi0 = x1[b * lda1 + 0]; xi1 = x1[b * lda1 + 1]; }
            else           { xi0 = sxi[br * 2 + 0];  xi1 = sxi[br * 2 + 1]; }
            #pragma unroll
            for (int q = 0; q < 4; q++) {
                int gg = q * HID + hc;
                gv[q] += xi0 * Wx[gg * INDIM + 0] + xi1 * Wx[gg * INDIM + 1];
            }
        }
        float ig = fast_sigmoid(gv[0]);
        float fg = fast_sigmoid(gv[1]);
        float gg = fast_tanh(gv[2]);
        float og = fast_sigmoid(gv[3]);
        int ci = b * HID + hc;
        float c = C[ci];
        c = fg * c + ig * gg;
        C[ci] = c;
        float h = og * fast_tanh(c);
        __nv_bfloat16 hh = __float2bfloat16(h);
        Houth[ci] = hh;
        Houtl[ci] = __float2bfloat16(h - __bfloat162float(hh));
    }
}

// One fused conversion kernel: 6 weight matrices -> split/tile-reordered planes.
__global__ void convert_all(const float* __restrict__ s0, const float* __restrict__ s1,
                            const float* __restrict__ s2, const float* __restrict__ s3,
                            const float* __restrict__ s4, const float* __restrict__ s5,
                            __nv_bfloat16* __restrict__ dhb,
                            __nv_bfloat16* __restrict__ dlb)
{
    const int WSZ = 4 * HID * HID;
    int m = blockIdx.x >> 12;                    // matrix index 0..5
    int j = ((blockIdx.x & 4095) << 8) + threadIdx.x;   // 0..WSZ-1
    const float* src;
    switch (m) {
        case 0: src = s0; break;
        case 1: src = s1; break;
        case 2: src = s2; break;
        case 3: src = s3; break;
        case 4: src = s4; break;
        default: src = s5; break;
    }
    int g = j >> 9, k = j & 511;
    int q = g >> 9, hc = g & 511;
    int tile = hc >> 4, hcd = hc & 15;
    int dr = m * WSZ + ((tile * 4 + q) * 16 + hcd) * HID + k;
    float w = src[j];
    __nv_bfloat16 h = __float2bfloat16(w);
    dhb[dr] = h;
    dlb[dr] = __float2bfloat16(w - __bfloat162float(h));
}

// Fused init: zero states + combined biases.
__global__ void setup_init(const float* __restrict__ eb0a, const float* __restrict__ eb0b,
                           const float* __restrict__ eb1a, const float* __restrict__ eb1b,
                           const float* __restrict__ db0a, const float* __restrict__ db0b,
                           const float* __restrict__ db1a, const float* __restrict__ db1b)
{
    int i = blockIdx.x * blockDim.x + threadIdx.x;
    if (i < BH) {
        g_zbf[i] = __ushort_as_bfloat16((unsigned short)0);
        g_c1[i] = 0.0f;
        g_c2[i] = 0.0f;
    }
    if (i < 4 * HID) {
        g_bsum[0][i] = eb0a[i] + eb0b[i];
        g_bsum[1][i] = eb1a[i] + eb1b[i];
        g_bsum[2][i] = db0a[i] + db0b[i];
        g_bsum[3][i] = db1a[i] + db1b[i];
    }
}

// pred[b,k] = (hi+lo)(h2[b,:]) . fcW[k,:] + fcb[k]  (final decoder step only)
__global__ void pred_kernel(const __nv_bfloat16* __restrict__ h2h,
                            const __nv_bfloat16* __restrict__ h2l,
                            const float* __restrict__ fcW,
                            const float* __restrict__ fcb,
                            float* __restrict__ out, int s)
{
    int warp = threadIdx.x >> 5;
    int lane = threadIdx.x & 31;
    int b = blockIdx.x * 4 + warp;
    float a0 = 0.0f, a1 = 0.0f;
    #pragma unroll
    for (int j = lane; j < HID; j += 32) {
        float h = __bfloat162float(h2h[b * HID + j]) + __bfloat162float(h2l[b * HID + j]);
        a0 += h * fcW[j];
        a1 += h * fcW[HID + j];
    }
    #pragma unroll
    for (int o = 16; o; o >>= 1) {
        a0 += __shfl_xor_sync(0xffffffffu, a0, o);
        a1 += __shfl_xor_sync(0xffffffffu, a1, o);
    }
    if (lane == 0) {
        out[b * HOR * 2 + s * 2 + 0] = a0 + fcb[0];
        out[b * HOR * 2 + s * 2 + 1] = a1 + fcb[1];
    }
}

extern "C" void kernel_launch(void* const* d_in, const int* in_sizes, int n_in,
                              void* d_out, int out_size)
{
    const float* x      = (const float*)d_in[0];
    const float* eWih0  = (const float*)d_in[1];
    const float* eWhh0  = (const float*)d_in[2];
    const float* ebih0  = (const float*)d_in[3];
    const float* ebhh0  = (const float*)d_in[4];
    const float* eWih1  = (const float*)d_in[5];
    const float* eWhh1  = (const float*)d_in[6];
    const float* ebih1  = (const float*)d_in[7];
    const float* ebhh1  = (const float*)d_in[8];
    const float* dWih0  = (const float*)d_in[9];
    const float* dWhh0  = (const float*)d_in[10];
    const float* dbih0  = (const float*)d_in[11];
    const float* dbhh0  = (const float*)d_in[12];
    const float* dWih1  = (const float*)d_in[13];
    const float* dWhh1  = (const float*)d_in[14];
    const float* dbih1  = (const float*)d_in[15];
    const float* dbhh1  = (const float*)d_in[16];
    const float* fcW    = (const float*)d_in[17];
    const float* fcb    = (const float*)d_in[18];
    float* out = (float*)d_out;

    __nv_bfloat16 *hs1h, *hs1l, *h1ah, *h1al, *h1bh, *h1bl;
    __nv_bfloat16 *h2ah, *h2al, *h2bh, *h2bl, *zb, *whb, *wlb;
    float *c1, *c2, *bsb;
    cudaGetSymbolAddress((void**)&hs1h, g_hs1h);
    cudaGetSymbolAddress((void**)&hs1l, g_hs1l);
    cudaGetSymbolAddress((void**)&h1ah, g_h1ah);
    cudaGetSymbolAddress((void**)&h1al, g_h1al);
    cudaGetSymbolAddress((void**)&h1bh, g_h1bh);
    cudaGetSymbolAddress((void**)&h1bl, g_h1bl);
    cudaGetSymbolAddress((void**)&h2ah, g_h2ah);
    cudaGetSymbolAddress((void**)&h2al, g_h2al);
    cudaGetSymbolAddress((void**)&h2bh, g_h2bh);
    cudaGetSymbolAddress((void**)&h2bl, g_h2bl);
    cudaGetSymbolAddress((void**)&zb,   g_zbf);
    cudaGetSymbolAddress((void**)&whb,  g_wh);
    cudaGetSymbolAddress((void**)&wlb,  g_wl);
    cudaGetSymbolAddress((void**)&c1,   g_c1);
    cudaGetSymbolAddress((void**)&c2,   g_c2);
    cudaGetSymbolAddress((void**)&bsb,  g_bsum);

    const int WSZ = 4 * HID * HID;
    __nv_bfloat16 *wh_eWhh0 = whb + 0 * WSZ, *wl_eWhh0 = wlb + 0 * WSZ;
    __nv_bfloat16 *wh_eWih1 = whb + 1 * WSZ, *wl_eWih1 = wlb + 1 * WSZ;
    __nv_bfloat16 *wh_eWhh1 = whb + 2 * WSZ, *wl_eWhh1 = wlb + 2 * WSZ;
    __nv_bfloat16 *wh_dWhh0 = whb + 3 * WSZ, *wl_dWhh0 = wlb + 3 * WSZ;
    __nv_bfloat16 *wh_dWih1 = whb + 4 * WSZ, *wl_dWih1 = wlb + 4 * WSZ;
    __nv_bfloat16 *wh_dWhh1 = whb + 5 * WSZ, *wl_dWhh1 = wlb + 5 * WSZ;
    float *bs_e0 = bsb + 0 * 4 * HID, *bs_e1 = bsb + 1 * 4 * HID;
    float *bs_d0 = bsb + 2 * 4 * HID, *bs_d1 = bsb + 3 * 4 * HID;

    cudaFuncSetAttribute(lstm_step, cudaFuncAttributeMaxDynamicSharedMemorySize,
                         SMEM_DYN);

    setup_init<<<(BH + 255) / 256, 256>>>(ebih0, ebhh0, ebih1, ebhh1,
                                          dbih0, dbhh0, dbih1, dbhh1);
    convert_all<<<6 * 4096, 256>>>(eWhh0, eWih1, eWhh1, dWhh0, dWih1, dWhh1,
                                   whb, wlb);

    dim3 grid(HID / 16, BSZ / BM);   // (32, 4) = 128 CTAs

    // Encoder layer 1 (mode 0). h chain lives in hs1 planes.
    for (int t = 0; t < TSEQ; t++) {
        const __nv_bfloat16* hinh = t ? (hs1h + (size_t)(t - 1) * BH) : zb;
        const __nv_bfloat16* hinl = t ? (hs1l + (size_t)(t - 1) * BH) : zb;
        lstm_step<<<grid, NTHR, SMEM_DYN>>>(
            nullptr, nullptr, nullptr, nullptr,
            x + t * INDIM, TSEQ * INDIM, eWih0,
            hinh, hinl, wh_eWhh0, wl_eWhh0, bs_e0,
            hs1h + (size_t)t * BH, hs1l + (size_t)t * BH, c1, 0, nullptr, 0);
    }
    // Encoder layer 2 (mode 1): final state ends in h2b (T even)
    for (int t = 0; t < TSEQ; t++) {
        const __nv_bfloat16* hinh = (t == 0) ? zb : ((t & 1) ? h2ah : h2bh);
        const __nv_bfloat16* hinl = (t == 0) ? zb : ((t & 1) ? h2al : h2bl);
        __nv_bfloat16* houth = (t & 1) ? h2bh : h2ah;
        __nv_bfloat16* houtl = (t & 1) ? h2bl : h2al;
        lstm_step<<<grid, NTHR, SMEM_DYN>>>(
            hs1h + (size_t)t * BH, hs1l + (size_t)t * BH, wh_eWih1, wl_eWih1,
            nullptr, 0, nullptr,
            hinh, hinl, wh_eWhh1, wl_eWhh1, bs_e1, houth, houtl, c2, 1, nullptr, 0);
    }
    // Decoder
    for (int s = 0; s < HOR; s++) {
        const __nv_bfloat16* h1inh = (s == 0) ? (hs1h + (size_t)(TSEQ - 1) * BH)
                                              : ((s & 1) ? h1ah : h1bh);
        const __nv_bfloat16* h1inl = (s == 0) ? (hs1l + (size_t)(TSEQ - 1) * BH)
                                              : ((s & 1) ? h1al : h1bl);
        __nv_bfloat16* h1outh = (s & 1) ? h1bh : h1ah;
        __nv_bfloat16* h1outl = (s & 1) ? h1bl : h1al;
        if (s == 0) {
            // dec_in0 = 0: mode 3 (no input term)
            lstm_step<<<grid, NTHR, SMEM_DYN>>>(
                nullptr, nullptr, nullptr, nullptr,
                nullptr, 0, nullptr,
                h1inh, h1inl, wh_dWhh0, wl_dWhh0, bs_d0, h1outh, h1outl,
                c1, 3, nullptr, 0);
        } else {
            // mode 2: xi = pred(h2 of step s-1), also writes out[., s-1]
            const __nv_bfloat16* h2ph = ((s - 1) & 1) ? h2bh : h2ah;
            const __nv_bfloat16* h2pl = ((s - 1) & 1) ? h2bl : h2al;
            lstm_step<<<grid, NTHR, SMEM_DYN>>>(
                h2ph, h2pl, (const __nv_bfloat16*)fcb, nullptr,
                fcW, 0, dWih0,
                h1inh, h1inl, wh_dWhh0, wl_dWhh0, bs_d0, h1outh, h1outl,
                c1, 2, out, s - 1);
        }

        const __nv_bfloat16* h2inh = (s == 0) ? h2bh : ((s & 1) ? h2ah : h2bh);
        const __nv_bfloat16* h2inl = (s == 0) ? h2bl : ((s & 1) ? h2al : h2bl);
        __nv_bfloat16* h2outh = (s & 1) ? h2bh : h2ah;
        __nv_bfloat16* h2outl = (s & 1) ? h2bl : h2al;
        lstm_step<<<grid, NTHR, SMEM_DYN>>>(
            h1outh, h1outl, wh_dWih1, wl_dWih1,
            nullptr, 0, nullptr,
            h2inh, h2inl, wh_dWhh1, wl_dWhh1, bs_d1, h2outh, h2outl, c2, 1,
            nullptr, 0);
    }
    // Final prediction (step 23) from h2 of s=23 (odd -> h2b)
    pred_kernel<<<BSZ / 4, 128>>>(h2bh, h2bl, fcW, fcb, out, HOR - 1);
}